// round 2
// baseline (speedup 1.0000x reference)
#include <cuda_runtime.h>

#define B_ 8
#define H_ 352
#define W_ 1216
#define PLANE (H_*W_)
#define MAXR 32

#define HPW 1280                    // padded width  (32 | 1216 | 32)
#define VPH 416                     // padded height (32 | 352  | 32)
#define NH (B_*H_*HPW)              // horizontal-table elements
#define NV (B_*VPH*W_)              // vertical-table elements

// Per-direction tables: .x = g = exp(-min(var,5))*mask ; .y = exp(+/-plog) ;
// .z = g*depth ; .w pad. Border cells are all-zero -> behave as masked pixels.
__device__ float4 g_dir0[NH]; // +w sources (w-n), var0, exp(+plog_h)
__device__ float4 g_dir1[NH]; // -w sources (w+n), var1, exp(-plog_h)
__device__ float4 g_dir2[NV]; // +h sources (h-n), var2, exp(+plog_v)
__device__ float4 g_dir3[NV]; // -h sources (h+n), var3, exp(-plog_v)

__global__ void prep_h(const float* __restrict__ pred_log,
                       const int*   __restrict__ mask,
                       const float* __restrict__ var,
                       const float* __restrict__ depth)
{
    int i = blockIdx.x * blockDim.x + threadIdx.x;
    if (i >= NH) return;
    int wp = i % HPW;
    int rh = i / HPW;               // b*H_ + h
    int w = wp - 32;
    if ((unsigned)w >= (unsigned)W_) {
        float4 z = make_float4(0.f, 0.f, 0.f, 0.f);
        g_dir0[i] = z; g_dir1[i] = z;
        return;
    }
    int b = rh / H_;
    int p = (rh - b * H_) * W_ + w;         // offset within plane
    int idx = rh * W_ + w;                  // b*PLANE + p
    float ph = pred_log[(size_t)b * 2 * PLANE + p];
    float m  = mask[idx] ? 1.f : 0.f;
    float v0 = var[(size_t)b * 4 * PLANE + p];
    float v1 = var[(size_t)b * 4 * PLANE + PLANE + p];
    float d  = depth[idx];
    float g0 = expf(-fminf(v0, 5.f)) * m;
    float g1 = expf(-fminf(v1, 5.f)) * m;
    g_dir0[i] = make_float4(g0, expf(ph),  g0 * d, 0.f);
    g_dir1[i] = make_float4(g1, expf(-ph), g1 * d, 0.f);
}

__global__ void prep_v(const float* __restrict__ pred_log,
                       const int*   __restrict__ mask,
                       const float* __restrict__ var,
                       const float* __restrict__ depth)
{
    int i = blockIdx.x * blockDim.x + threadIdx.x;
    if (i >= NV) return;
    int w   = i % W_;
    int rhp = i / W_;               // b*VPH + hp
    int b   = rhp / VPH;
    int h   = (rhp - b * VPH) - 32;
    if ((unsigned)h >= (unsigned)H_) {
        float4 z = make_float4(0.f, 0.f, 0.f, 0.f);
        g_dir2[i] = z; g_dir3[i] = z;
        return;
    }
    int p = h * W_ + w;
    int idx = b * PLANE + p;
    float pv = pred_log[(size_t)b * 2 * PLANE + PLANE + p];
    float m  = mask[idx] ? 1.f : 0.f;
    float v2 = var[(size_t)b * 4 * PLANE + 2 * PLANE + p];
    float v3 = var[(size_t)b * 4 * PLANE + 3 * PLANE + p];
    float d  = depth[idx];
    float g2 = expf(-fminf(v2, 5.f)) * m;
    float g3 = expf(-fminf(v3, 5.f)) * m;
    g_dir2[i] = make_float4(g2, expf(pv),  g2 * d, 0.f);
    g_dir3[i] = make_float4(g3, expf(-pv), g3 * d, 0.f);
}

__global__ void __launch_bounds__(256)
crf_kernel(const int*   __restrict__ mask,
           const float* __restrict__ depthin,
           const float* __restrict__ lam_p,
           float*       __restrict__ out)
{
    int w = blockIdx.x * blockDim.x + threadIdx.x;
    if (w >= W_) return;
    int h = blockIdx.y;
    int b = blockIdx.z;
    int idx = (b * H_ + h) * W_ + w;

    float din = depthin[idx];
    if (mask[idx] == 0) { out[idx] = din; return; }

    int bh = (b * H_ + h) * HPW + 32 + w;       // center in horizontal tables
    int bv = (b * VPH + 32 + h) * W_ + w;       // center in vertical tables

    float aw = 0.f, awd = 0.f;

    // +w: product includes the source step (multiply before use).
    {
        float A = 1.f, P = 1.f;
        #pragma unroll 8
        for (int n = 1; n <= MAXR; ++n) {
            float4 t = g_dir0[bh - n];
            P *= t.y;
            awd += t.z * P;
            aw  += t.x * A;
            if (t.x == 0.f) { A = 0.f; P = 0.f; }
        }
    }
    // -w: product excludes the source step (center term first, multiply after use).
    {
        float A = 1.f, P = g_dir1[bh].y;
        #pragma unroll 8
        for (int n = 1; n <= MAXR; ++n) {
            float4 t = g_dir1[bh + n];
            awd += t.z * P;
            aw  += t.x * A;
            P *= t.y;
            if (t.x == 0.f) { A = 0.f; P = 0.f; }
        }
    }
    // +h
    {
        float A = 1.f, P = 1.f;
        #pragma unroll 8
        for (int n = 1; n <= MAXR; ++n) {
            float4 t = g_dir2[bv - n * W_];
            P *= t.y;
            awd += t.z * P;
            aw  += t.x * A;
            if (t.x == 0.f) { A = 0.f; P = 0.f; }
        }
    }
    // -h
    {
        float A = 1.f, P = g_dir3[bv].y;
        #pragma unroll 8
        for (int n = 1; n <= MAXR; ++n) {
            float4 t = g_dir3[bv + n * W_];
            awd += t.z * P;
            aw  += t.x * A;
            P *= t.y;
            if (t.x == 0.f) { A = 0.f; P = 0.f; }
        }
    }

    float o = din;
    if (aw > 0.f) {
        float lat = awd / fmaxf(aw, 1e-12f);
        if (lat > 0.f) {
            float lam = lam_p[0];
            o = din * (1.f - lam) + lat * lam;
        }
    }
    out[idx] = o;
}

extern "C" void kernel_launch(void* const* d_in, const int* in_sizes, int n_in,
                              void* d_out, int out_size)
{
    const float* pred_log = (const float*)d_in[0];
    const int*   mask     = (const int*)  d_in[1];
    const float* variance = (const float*)d_in[2];
    const float* depthin  = (const float*)d_in[3];
    const float* lam      = (const float*)d_in[4];
    float* out = (float*)d_out;

    const int T = 256;
    prep_h<<<(NH + T - 1) / T, T>>>(pred_log, mask, variance, depthin);
    prep_v<<<(NV + T - 1) / T, T>>>(pred_log, mask, variance, depthin);

    dim3 grid((W_ + T - 1) / T, H_, B_);
    crf_kernel<<<grid, T>>>(mask, depthin, lam, out);
}

// round 3
// speedup vs baseline: 1.4387x; 1.4387x over previous
#include <cuda_runtime.h>

#define B_ 8
#define H_ 352
#define W_ 1216
#define PLANE (H_*W_)
#define MAXR 32

#define HPW 1280                    // padded width  (32 | 1216 | 32)
#define VPH 416                     // padded height (32 | 352  | 32)
#define NH (B_*H_*HPW)
#define NV (B_*VPH*W_)

// Split per-direction tables (12 B/step in the hot loop):
//   E*  = exp(+/- plog)                          (per-step log-gradient factor)
//   GD* = (g, g*depth), g = exp(-min(var,5))*mask (0 iff masked / border)
__device__ float  E0[NH];  __device__ float2 GD0[NH]; // +w, var0, exp(+plog_h)
__device__ float  E1[NH];  __device__ float2 GD1[NH]; // -w, var1, exp(-plog_h)
__device__ float  E2[NV];  __device__ float2 GD2[NV]; // +h, var2, exp(+plog_v)
__device__ float  E3[NV];  __device__ float2 GD3[NV]; // -h, var3, exp(-plog_v)

__global__ void prep_h(const float* __restrict__ pred_log,
                       const int*   __restrict__ mask,
                       const float* __restrict__ var,
                       const float* __restrict__ depth)
{
    int i = blockIdx.x * blockDim.x + threadIdx.x;
    if (i >= NH) return;
    int wp = i % HPW;
    int rh = i / HPW;               // b*H_ + h
    int w = wp - 32;
    if ((unsigned)w >= (unsigned)W_) {
        E0[i] = 0.f; E1[i] = 0.f;
        GD0[i] = make_float2(0.f, 0.f); GD1[i] = make_float2(0.f, 0.f);
        return;
    }
    int b = rh / H_;
    int p = (rh - b * H_) * W_ + w;
    int idx = rh * W_ + w;
    float ph = pred_log[(size_t)b * 2 * PLANE + p];
    float m  = mask[idx] ? 1.f : 0.f;
    float v0 = var[(size_t)b * 4 * PLANE + p];
    float v1 = var[(size_t)b * 4 * PLANE + PLANE + p];
    float d  = depth[idx];
    float g0 = expf(-fminf(v0, 5.f)) * m;
    float g1 = expf(-fminf(v1, 5.f)) * m;
    float e  = expf(ph);
    E0[i] = e;
    E1[i] = 1.0f / e == 0.f ? 0.f : expf(-ph);   // exact exp(-ph) (avoid rcp rounding)
    GD0[i] = make_float2(g0, g0 * d);
    GD1[i] = make_float2(g1, g1 * d);
}

__global__ void prep_v(const float* __restrict__ pred_log,
                       const int*   __restrict__ mask,
                       const float* __restrict__ var,
                       const float* __restrict__ depth)
{
    int i = blockIdx.x * blockDim.x + threadIdx.x;
    if (i >= NV) return;
    int w   = i % W_;
    int rhp = i / W_;               // b*VPH + hp
    int b   = rhp / VPH;
    int h   = (rhp - b * VPH) - 32;
    if ((unsigned)h >= (unsigned)H_) {
        E2[i] = 0.f; E3[i] = 0.f;
        GD2[i] = make_float2(0.f, 0.f); GD3[i] = make_float2(0.f, 0.f);
        return;
    }
    int p = h * W_ + w;
    int idx = b * PLANE + p;
    float pv = pred_log[(size_t)b * 2 * PLANE + PLANE + p];
    float m  = mask[idx] ? 1.f : 0.f;
    float v2 = var[(size_t)b * 4 * PLANE + 2 * PLANE + p];
    float v3 = var[(size_t)b * 4 * PLANE + 3 * PLANE + p];
    float d  = depth[idx];
    float g2 = expf(-fminf(v2, 5.f)) * m;
    float g3 = expf(-fminf(v3, 5.f)) * m;
    E2[i] = expf(pv);
    E3[i] = expf(-pv);
    GD2[i] = make_float2(g2, g2 * d);
    GD3[i] = make_float2(g3, g3 * d);
}

// One directional walk: batches of 4 independent loads, kill-selects inside the
// batch, early break between batches. INCL = product includes the source step.
// S = signed element stride toward the sources.
template<bool INCL, int S>
__device__ __forceinline__ void walk(const float* __restrict__ E,
                                     const float2* __restrict__ GD,
                                     int c, float& aw, float& awd)
{
    float P = INCL ? 1.f : E[c];
    float A = 1.f;
    for (int n0 = 1; n0 <= MAXR; n0 += 4) {
        float  e[4];
        float2 g[4];
        #pragma unroll
        for (int j = 0; j < 4; ++j) {
            int off = c + (n0 + j) * S;
            e[j] = E[off];
            g[j] = GD[off];
        }
        #pragma unroll
        for (int j = 0; j < 4; ++j) {
            if (INCL) P *= e[j];
            awd += g[j].y * P;
            aw  += g[j].x * A;
            if (!INCL) P *= e[j];
            if (g[j].x == 0.f) { A = 0.f; P = 0.f; }
        }
        if (A == 0.f) break;
    }
}

__global__ void __launch_bounds__(256)
crf_kernel(const int*   __restrict__ mask,
           const float* __restrict__ depthin,
           const float* __restrict__ lam_p,
           float*       __restrict__ out)
{
    int w = blockIdx.x * blockDim.x + threadIdx.x;
    if (w >= W_) return;
    int h = blockIdx.y;
    int b = blockIdx.z;
    int idx = (b * H_ + h) * W_ + w;

    float din = depthin[idx];
    if (mask[idx] == 0) { out[idx] = din; return; }

    int bh = (b * H_ + h) * HPW + 32 + w;       // center in horizontal tables
    int bv = (b * VPH + 32 + h) * W_ + w;       // center in vertical tables

    float aw = 0.f, awd = 0.f;
    walk<true,  -1 >(E0, GD0, bh, aw, awd);     // +w
    walk<false, +1 >(E1, GD1, bh, aw, awd);     // -w
    walk<true,  -W_>(E2, GD2, bv, aw, awd);     // +h
    walk<false, +W_>(E3, GD3, bv, aw, awd);     // -h

    float o = din;
    if (aw > 0.f) {
        float lat = awd / fmaxf(aw, 1e-12f);
        if (lat > 0.f) {
            float lam = lam_p[0];
            o = din * (1.f - lam) + lat * lam;
        }
    }
    out[idx] = o;
}

extern "C" void kernel_launch(void* const* d_in, const int* in_sizes, int n_in,
                              void* d_out, int out_size)
{
    const float* pred_log = (const float*)d_in[0];
    const int*   mask     = (const int*)  d_in[1];
    const float* variance = (const float*)d_in[2];
    const float* depthin  = (const float*)d_in[3];
    const float* lam      = (const float*)d_in[4];
    float* out = (float*)d_out;

    const int T = 256;
    prep_h<<<(NH + T - 1) / T, T>>>(pred_log, mask, variance, depthin);
    prep_v<<<(NV + T - 1) / T, T>>>(pred_log, mask, variance, depthin);

    dim3 grid((W_ + T - 1) / T, H_, B_);
    crf_kernel<<<grid, T>>>(mask, depthin, lam, out);
}